// round 1
// baseline (speedup 1.0000x reference)
#include <cuda_runtime.h>
#include <math.h>

#define D_MODEL 1024
#define F_FFN   4096
#define B_SZ    4
#define S_LEN   2048
#define N_HEADS 16
#define DK      64
#define M_ROWS  (B_SZ * S_LEN)   // 8192
#define LN_EPS  1e-6f

// ---------------- scratch (no allocs allowed) ----------------
__device__ float g_xn [(size_t)M_ROWS * D_MODEL];
__device__ float g_q  [(size_t)M_ROWS * D_MODEL];
__device__ float g_k  [(size_t)M_ROWS * D_MODEL];
__device__ float g_v  [(size_t)M_ROWS * D_MODEL];
__device__ float g_ctx[(size_t)M_ROWS * D_MODEL];
__device__ float g_h  [(size_t)M_ROWS * D_MODEL];
__device__ float g_xn2[(size_t)M_ROWS * D_MODEL];
__device__ float g_mid[(size_t)M_ROWS * F_FFN];

// ---------------- LayerNorm (torch semantics: ddof=1, eps added to std) ----
__global__ void __launch_bounds__(256) ln_kernel(
    const float* __restrict__ x,
    const float* __restrict__ alpha,
    const float* __restrict__ beta,
    float* __restrict__ out)
{
    __shared__ float red[32];
    const int row = blockIdx.x;
    const int tid = threadIdx.x;

    const float4 v = ((const float4*)(x + (size_t)row * D_MODEL))[tid];
    float s  = v.x + v.y + v.z + v.w;
    float s2 = v.x * v.x + v.y * v.y + v.z * v.z + v.w * v.w;
    #pragma unroll
    for (int off = 16; off > 0; off >>= 1) {
        s  += __shfl_xor_sync(0xffffffffu, s,  off);
        s2 += __shfl_xor_sync(0xffffffffu, s2, off);
    }
    const int warp = tid >> 5;
    if ((tid & 31) == 0) { red[warp] = s; red[8 + warp] = s2; }
    __syncthreads();
    if (tid == 0) {
        float ts = 0.f, ts2 = 0.f;
        #pragma unroll
        for (int i = 0; i < 8; i++) { ts += red[i]; ts2 += red[8 + i]; }
        const float mean = ts * (1.0f / (float)D_MODEL);
        float var = (ts2 - (float)D_MODEL * mean * mean) * (1.0f / (float)(D_MODEL - 1));
        var = fmaxf(var, 0.0f);
        red[16] = mean;
        red[17] = 1.0f / (sqrtf(var) + LN_EPS);
    }
    __syncthreads();
    const float mean = red[16], inv = red[17];
    const float4 a = ((const float4*)alpha)[tid];
    const float4 b = ((const float4*)beta)[tid];
    float4 o;
    o.x = a.x * (v.x - mean) * inv + b.x;
    o.y = a.y * (v.y - mean) * inv + b.y;
    o.z = a.z * (v.z - mean) * inv + b.z;
    o.w = a.w * (v.w - mean) * inv + b.w;
    ((float4*)(out + (size_t)row * D_MODEL))[tid] = o;
}

// ---------------- SGEMM: C[M,N] = op(A[M,K] @ B[K,N] + bias [+ res]) --------
// 128x128 block tile, Kt=8, 256 threads, 8x8 per thread. Global prefetch.
template<bool RELU, bool RES>
__global__ void __launch_bounds__(256) sgemm_kernel(
    const float* __restrict__ A, const float* __restrict__ B,
    const float* __restrict__ bias, const float* __restrict__ res,
    float* __restrict__ C, int M, int N, int K)
{
    __shared__ float As[8][128];
    __shared__ float Bs[8][128];

    const int tid = threadIdx.x;
    const int tx = tid & 15;     // 0..15 : column group
    const int ty = tid >> 4;     // 0..15 : row group
    const int bx = blockIdx.x;
    const int by = blockIdx.y;

    const float* Ab = A + (size_t)(by * 128) * K;
    const float* Bb = B + bx * 128;

    const int arow = tid >> 1, ac4 = (tid & 1) * 4;
    const int brow = tid >> 5, bc4 = (tid & 31) * 4;

    float acc[8][8];
    #pragma unroll
    for (int i = 0; i < 8; i++)
        #pragma unroll
        for (int j = 0; j < 8; j++) acc[i][j] = 0.f;

    float4 av = *(const float4*)(Ab + (size_t)arow * K + ac4);
    float4 bv = *(const float4*)(Bb + (size_t)brow * N + bc4);

    for (int kt = 0; kt < K; kt += 8) {
        As[ac4 + 0][arow] = av.x;
        As[ac4 + 1][arow] = av.y;
        As[ac4 + 2][arow] = av.z;
        As[ac4 + 3][arow] = av.w;
        *(float4*)&Bs[brow][bc4] = bv;
        __syncthreads();

        if (kt + 8 < K) {
            av = *(const float4*)(Ab + (size_t)arow * K + (kt + 8) + ac4);
            bv = *(const float4*)(Bb + (size_t)(kt + 8 + brow) * N + bc4);
        }

        #pragma unroll
        for (int kk = 0; kk < 8; kk++) {
            float a[8], b[8];
            *(float4*)&a[0] = *(const float4*)&As[kk][ty * 8];
            *(float4*)&a[4] = *(const float4*)&As[kk][ty * 8 + 4];
            *(float4*)&b[0] = *(const float4*)&Bs[kk][tx * 4];
            *(float4*)&b[4] = *(const float4*)&Bs[kk][64 + tx * 4];
            #pragma unroll
            for (int i = 0; i < 8; i++)
                #pragma unroll
                for (int j = 0; j < 8; j++)
                    acc[i][j] = fmaf(a[i], b[j], acc[i][j]);
        }
        __syncthreads();
    }

    #pragma unroll
    for (int i = 0; i < 8; i++) {
        const size_t r = (size_t)(by * 128 + ty * 8 + i);
        #pragma unroll
        for (int jh = 0; jh < 2; jh++) {
            const int c = bx * 128 + jh * 64 + tx * 4;
            float4 o;
            o.x = acc[i][jh * 4 + 0];
            o.y = acc[i][jh * 4 + 1];
            o.z = acc[i][jh * 4 + 2];
            o.w = acc[i][jh * 4 + 3];
            const float4 bb = *(const float4*)(bias + c);
            o.x += bb.x; o.y += bb.y; o.z += bb.z; o.w += bb.w;
            if (RES) {
                const float4 rv = *(const float4*)(res + r * N + c);
                o.x += rv.x; o.y += rv.y; o.z += rv.z; o.w += rv.w;
            }
            if (RELU) {
                o.x = fmaxf(o.x, 0.f); o.y = fmaxf(o.y, 0.f);
                o.z = fmaxf(o.z, 0.f); o.w = fmaxf(o.w, 0.f);
            }
            *(float4*)(C + r * N + c) = o;
        }
    }
}

// ---------------- Flash-style attention ------------------------------------
// Grid: (S/128, H, B). Block 256 threads. Q tile 128 x 64, K/V tiles 64 x 64.
// Thread map: tx = tid%8 owns k cols {j*8+tx} and out dims {tx*8..tx*8+7};
//             ty = tid/8 owns q rows {ty*4..ty*4+3}.
#define QTILE 128
#define KTILE 64
#define QS 68     // Qs row stride (floats)
#define KS 68     // Ks row stride
#define VS 64     // Vs row stride
#define PS 68     // Ps row stride
#define ATTN_SMEM ((QTILE*QS + KTILE*KS + KTILE*VS + QTILE*PS + KTILE) * 4)

__global__ void __launch_bounds__(256) attn_kernel(
    const float* __restrict__ Q, const float* __restrict__ K,
    const float* __restrict__ V, const int* __restrict__ mask,
    float* __restrict__ O)
{
    extern __shared__ float sm[];
    float* Qs = sm;                        // 128*68
    float* Ks = Qs + QTILE * QS;           // 64*68
    float* Vs = Ks + KTILE * KS;           // 64*64
    float* Ps = Vs + KTILE * VS;           // 128*68
    float* Ms = Ps + QTILE * PS;           // 64

    const int b  = blockIdx.z;
    const int h  = blockIdx.y;
    const int q0 = blockIdx.x * QTILE;
    const int tid = threadIdx.x;
    const int tx = tid & 7;
    const int ty = tid >> 3;

    // Load Q tile (128 x 64 floats = 2048 float4)
    const size_t baseQ = ((size_t)(b * S_LEN + q0)) * D_MODEL + h * DK;
    #pragma unroll
    for (int p = 0; p < 8; p++) {
        const int f = p * 256 + tid;
        const int r = f >> 4, c4 = f & 15;
        *(float4*)&Qs[r * QS + c4 * 4] =
            *(const float4*)(Q + baseQ + (size_t)r * D_MODEL + c4 * 4);
    }

    float m[4], l[4];
    #pragma unroll
    for (int i = 0; i < 4; i++) { m[i] = -1e30f; l[i] = 0.f; }
    float acc[4][8];
    #pragma unroll
    for (int i = 0; i < 4; i++)
        #pragma unroll
        for (int j = 0; j < 8; j++) acc[i][j] = 0.f;

    __syncthreads();

    for (int kt = 0; kt < S_LEN; kt += KTILE) {
        // Load K/V tiles (64 x 64 each) + mask
        const size_t baseK = ((size_t)(b * S_LEN + kt)) * D_MODEL + h * DK;
        #pragma unroll
        for (int p = 0; p < 4; p++) {
            const int f = p * 256 + tid;
            const int r = f >> 4, c4 = f & 15;
            *(float4*)&Ks[r * KS + c4 * 4] =
                *(const float4*)(K + baseK + (size_t)r * D_MODEL + c4 * 4);
            *(float4*)&Vs[r * VS + c4 * 4] =
                *(const float4*)(V + baseK + (size_t)r * D_MODEL + c4 * 4);
        }
        if (tid < KTILE)
            Ms[tid] = (mask[b * S_LEN + kt + tid] == 0) ? -1e9f : 0.f;
        __syncthreads();

        // Scores: s[i][j] for q rows ty*4+i, k cols j*8+tx
        float s[4][8];
        #pragma unroll
        for (int i = 0; i < 4; i++)
            #pragma unroll
            for (int j = 0; j < 8; j++) s[i][j] = 0.f;

        #pragma unroll
        for (int d = 0; d < DK; d += 4) {
            float4 qv[4];
            #pragma unroll
            for (int i = 0; i < 4; i++)
                qv[i] = *(const float4*)&Qs[(ty * 4 + i) * QS + d];
            #pragma unroll
            for (int j = 0; j < 8; j++) {
                const float4 kv = *(const float4*)&Ks[(j * 8 + tx) * KS + d];
                #pragma unroll
                for (int i = 0; i < 4; i++) {
                    s[i][j] = fmaf(qv[i].x, kv.x, s[i][j]);
                    s[i][j] = fmaf(qv[i].y, kv.y, s[i][j]);
                    s[i][j] = fmaf(qv[i].z, kv.z, s[i][j]);
                    s[i][j] = fmaf(qv[i].w, kv.w, s[i][j]);
                }
            }
        }
        #pragma unroll
        for (int i = 0; i < 4; i++)
            #pragma unroll
            for (int j = 0; j < 8; j++)
                s[i][j] = s[i][j] * 0.125f + Ms[j * 8 + tx];

        // Online softmax (rows reduced across the 8 tx lanes)
        #pragma unroll
        for (int i = 0; i < 4; i++) {
            float rm = s[i][0];
            #pragma unroll
            for (int j = 1; j < 8; j++) rm = fmaxf(rm, s[i][j]);
            #pragma unroll
            for (int off = 1; off < 8; off <<= 1)
                rm = fmaxf(rm, __shfl_xor_sync(0xffffffffu, rm, off));
            const float newm = fmaxf(m[i], rm);
            const float factor = __expf(m[i] - newm);
            m[i] = newm;
            float rs = 0.f;
            #pragma unroll
            for (int j = 0; j < 8; j++) {
                s[i][j] = __expf(s[i][j] - newm);
                rs += s[i][j];
            }
            #pragma unroll
            for (int off = 1; off < 8; off <<= 1)
                rs += __shfl_xor_sync(0xffffffffu, rs, off);
            l[i] = l[i] * factor + rs;
            #pragma unroll
            for (int j = 0; j < 8; j++) acc[i][j] *= factor;
            #pragma unroll
            for (int j = 0; j < 8; j++)
                Ps[(ty * 4 + i) * PS + j * 8 + tx] = s[i][j];
        }
        __syncthreads();

        // O += P @ V : thread owns (q rows ty*4+i) x (d cols tx*8..+7)
        #pragma unroll
        for (int j = 0; j < KTILE; j += 4) {
            float pa[4][4];
            #pragma unroll
            for (int i = 0; i < 4; i++)
                *(float4*)&pa[i][0] = *(const float4*)&Ps[(ty * 4 + i) * PS + j];
            #pragma unroll
            for (int jj = 0; jj < 4; jj++) {
                const float4 v0 = *(const float4*)&Vs[(j + jj) * VS + tx * 8];
                const float4 v1 = *(const float4*)&Vs[(j + jj) * VS + tx * 8 + 4];
                #pragma unroll
                for (int i = 0; i < 4; i++) {
                    const float p = pa[i][jj];
                    acc[i][0] = fmaf(p, v0.x, acc[i][0]);
                    acc[i][1] = fmaf(p, v0.y, acc[i][1]);
                    acc[i][2] = fmaf(p, v0.z, acc[i][2]);
                    acc[i][3] = fmaf(p, v0.w, acc[i][3]);
                    acc[i][4] = fmaf(p, v1.x, acc[i][4]);
                    acc[i][5] = fmaf(p, v1.y, acc[i][5]);
                    acc[i][6] = fmaf(p, v1.z, acc[i][6]);
                    acc[i][7] = fmaf(p, v1.w, acc[i][7]);
                }
            }
        }
        __syncthreads();
    }

    // Finalize: ctx[b, q, h*64 + d] = acc / l
    #pragma unroll
    for (int i = 0; i < 4; i++) {
        const float invl = 1.0f / l[i];
        const size_t q = (size_t)(b * S_LEN + q0 + ty * 4 + i);
        float* orow = O + q * D_MODEL + h * DK + tx * 8;
        float4 o0, o1;
        o0.x = acc[i][0] * invl; o0.y = acc[i][1] * invl;
        o0.z = acc[i][2] * invl; o0.w = acc[i][3] * invl;
        o1.x = acc[i][4] * invl; o1.y = acc[i][5] * invl;
        o1.z = acc[i][6] * invl; o1.w = acc[i][7] * invl;
        *(float4*)orow = o0;
        *(float4*)(orow + 4) = o1;
    }
}

// ---------------- launch ---------------------------------------------------
extern "C" void kernel_launch(void* const* d_in, const int* in_sizes, int n_in,
                              void* d_out, int out_size)
{
    const float* x   = (const float*)d_in[0];
    const int*   msk = (const int*)  d_in[1];
    const float* wq  = (const float*)d_in[2];
    const float* bq  = (const float*)d_in[3];
    const float* wk  = (const float*)d_in[4];
    const float* bk  = (const float*)d_in[5];
    const float* wv  = (const float*)d_in[6];
    const float* bv  = (const float*)d_in[7];
    const float* wo  = (const float*)d_in[8];
    const float* bo  = (const float*)d_in[9];
    const float* w1  = (const float*)d_in[10];
    const float* b1  = (const float*)d_in[11];
    const float* w2  = (const float*)d_in[12];
    const float* b2  = (const float*)d_in[13];
    const float* l1a = (const float*)d_in[14];
    const float* l1b = (const float*)d_in[15];
    const float* l2a = (const float*)d_in[16];
    const float* l2b = (const float*)d_in[17];
    float* out = (float*)d_out;

    float *xn, *q, *k, *v, *ctx, *h, *xn2, *mid;
    cudaGetSymbolAddress((void**)&xn,  g_xn);
    cudaGetSymbolAddress((void**)&q,   g_q);
    cudaGetSymbolAddress((void**)&k,   g_k);
    cudaGetSymbolAddress((void**)&v,   g_v);
    cudaGetSymbolAddress((void**)&ctx, g_ctx);
    cudaGetSymbolAddress((void**)&h,   g_h);
    cudaGetSymbolAddress((void**)&xn2, g_xn2);
    cudaGetSymbolAddress((void**)&mid, g_mid);

    cudaFuncSetAttribute(attn_kernel,
        cudaFuncAttributeMaxDynamicSharedMemorySize, ATTN_SMEM);

    // 1. ln1
    ln_kernel<<<M_ROWS, 256>>>(x, l1a, l1b, xn);
    // 2. QKV projections
    sgemm_kernel<false, false><<<dim3(D_MODEL/128, M_ROWS/128), 256>>>(
        xn, wq, bq, nullptr, q, M_ROWS, D_MODEL, D_MODEL);
    sgemm_kernel<false, false><<<dim3(D_MODEL/128, M_ROWS/128), 256>>>(
        xn, wk, bk, nullptr, k, M_ROWS, D_MODEL, D_MODEL);
    sgemm_kernel<false, false><<<dim3(D_MODEL/128, M_ROWS/128), 256>>>(
        xn, wv, bv, nullptr, v, M_ROWS, D_MODEL, D_MODEL);
    // 3. attention
    attn_kernel<<<dim3(S_LEN/QTILE, N_HEADS, B_SZ), 256, ATTN_SMEM>>>(
        q, k, v, msk, ctx);
    // 4. output projection + residual with x
    sgemm_kernel<false, true><<<dim3(D_MODEL/128, M_ROWS/128), 256>>>(
        ctx, wo, bo, x, h, M_ROWS, D_MODEL, D_MODEL);
    // 5. ln2
    ln_kernel<<<M_ROWS, 256>>>(h, l2a, l2b, xn2);
    // 6. FFN up + relu
    sgemm_kernel<true, false><<<dim3(F_FFN/128, M_ROWS/128), 256>>>(
        xn2, w1, b1, nullptr, mid, M_ROWS, F_FFN, D_MODEL);
    // 7. FFN down + residual with h -> out
    sgemm_kernel<false, true><<<dim3(D_MODEL/128, M_ROWS/128), 256>>>(
        mid, w2, b2, h, out, M_ROWS, D_MODEL, F_FFN);
}

// round 2
// speedup vs baseline: 1.0008x; 1.0008x over previous
#include <cuda_runtime.h>
#include <math.h>

#define D_MODEL 1024
#define F_FFN   4096
#define B_SZ    4
#define S_LEN   2048
#define N_HEADS 16
#define DK      64
#define M_ROWS  (B_SZ * S_LEN)   // 8192
#define LN_EPS  1e-6f

// ---------------- scratch (no allocs allowed) ----------------
__device__ float g_xn [(size_t)M_ROWS * D_MODEL];
__device__ float g_q  [(size_t)M_ROWS * D_MODEL];
__device__ float g_k  [(size_t)M_ROWS * D_MODEL];
__device__ float g_v  [(size_t)M_ROWS * D_MODEL];
__device__ float g_ctx[(size_t)M_ROWS * D_MODEL];
__device__ float g_h  [(size_t)M_ROWS * D_MODEL];
__device__ float g_xn2[(size_t)M_ROWS * D_MODEL];
__device__ float g_mid[(size_t)M_ROWS * F_FFN];

// ---------------- LayerNorm (torch semantics: ddof=1, eps added to std) ----
__global__ void __launch_bounds__(256) ln_kernel(
    const float* __restrict__ x,
    const float* __restrict__ alpha,
    const float* __restrict__ beta,
    float* __restrict__ out)
{
    __shared__ float red[32];
    const int row = blockIdx.x;
    const int tid = threadIdx.x;

    const float4 v = ((const float4*)(x + (size_t)row * D_MODEL))[tid];
    float s  = v.x + v.y + v.z + v.w;
    float s2 = v.x * v.x + v.y * v.y + v.z * v.z + v.w * v.w;
    #pragma unroll
    for (int off = 16; off > 0; off >>= 1) {
        s  += __shfl_xor_sync(0xffffffffu, s,  off);
        s2 += __shfl_xor_sync(0xffffffffu, s2, off);
    }
    const int warp = tid >> 5;
    if ((tid & 31) == 0) { red[warp] = s; red[8 + warp] = s2; }
    __syncthreads();
    if (tid == 0) {
        float ts = 0.f, ts2 = 0.f;
        #pragma unroll
        for (int i = 0; i < 8; i++) { ts += red[i]; ts2 += red[8 + i]; }
        const float mean = ts * (1.0f / (float)D_MODEL);
        float var = (ts2 - (float)D_MODEL * mean * mean) * (1.0f / (float)(D_MODEL - 1));
        var = fmaxf(var, 0.0f);
        red[16] = mean;
        red[17] = 1.0f / (sqrtf(var) + LN_EPS);
    }
    __syncthreads();
    const float mean = red[16], inv = red[17];
    const float4 a = ((const float4*)alpha)[tid];
    const float4 b = ((const float4*)beta)[tid];
    float4 o;
    o.x = a.x * (v.x - mean) * inv + b.x;
    o.y = a.y * (v.y - mean) * inv + b.y;
    o.z = a.z * (v.z - mean) * inv + b.z;
    o.w = a.w * (v.w - mean) * inv + b.w;
    ((float4*)(out + (size_t)row * D_MODEL))[tid] = o;
}

// ---------------- SGEMM: C[M,N] = op(A[M,K] @ B[K,N] + bias [+ res]) --------
// 128x128 block tile, Kt=8, 256 threads, 8x8 per thread. Global prefetch.
template<bool RELU, bool RES>
__global__ void __launch_bounds__(256) sgemm_kernel(
    const float* __restrict__ A, const float* __restrict__ B,
    const float* __restrict__ bias, const float* __restrict__ res,
    float* __restrict__ C, int M, int N, int K)
{
    __shared__ float As[8][128];
    __shared__ float Bs[8][128];

    const int tid = threadIdx.x;
    const int tx = tid & 15;     // 0..15 : column group
    const int ty = tid >> 4;     // 0..15 : row group
    const int bx = blockIdx.x;
    const int by = blockIdx.y;

    const float* Ab = A + (size_t)(by * 128) * K;
    const float* Bb = B + bx * 128;

    const int arow = tid >> 1, ac4 = (tid & 1) * 4;
    const int brow = tid >> 5, bc4 = (tid & 31) * 4;

    float acc[8][8];
    #pragma unroll
    for (int i = 0; i < 8; i++)
        #pragma unroll
        for (int j = 0; j < 8; j++) acc[i][j] = 0.f;

    float4 av = *(const float4*)(Ab + (size_t)arow * K + ac4);
    float4 bv = *(const float4*)(Bb + (size_t)brow * N + bc4);

    for (int kt = 0; kt < K; kt += 8) {
        As[ac4 + 0][arow] = av.x;
        As[ac4 + 1][arow] = av.y;
        As[ac4 + 2][arow] = av.z;
        As[ac4 + 3][arow] = av.w;
        *(float4*)&Bs[brow][bc4] = bv;
        __syncthreads();

        if (kt + 8 < K) {
            av = *(const float4*)(Ab + (size_t)arow * K + (kt + 8) + ac4);
            bv = *(const float4*)(Bb + (size_t)(kt + 8 + brow) * N + bc4);
        }

        #pragma unroll
        for (int kk = 0; kk < 8; kk++) {
            float a[8], b[8];
            *(float4*)&a[0] = *(const float4*)&As[kk][ty * 8];
            *(float4*)&a[4] = *(const float4*)&As[kk][ty * 8 + 4];
            *(float4*)&b[0] = *(const float4*)&Bs[kk][tx * 4];
            *(float4*)&b[4] = *(const float4*)&Bs[kk][64 + tx * 4];
            #pragma unroll
            for (int i = 0; i < 8; i++)
                #pragma unroll
                for (int j = 0; j < 8; j++)
                    acc[i][j] = fmaf(a[i], b[j], acc[i][j]);
        }
        __syncthreads();
    }

    #pragma unroll
    for (int i = 0; i < 8; i++) {
        const size_t r = (size_t)(by * 128 + ty * 8 + i);
        #pragma unroll
        for (int jh = 0; jh < 2; jh++) {
            const int c = bx * 128 + jh * 64 + tx * 4;
            float4 o;
            o.x = acc[i][jh * 4 + 0];
            o.y = acc[i][jh * 4 + 1];
            o.z = acc[i][jh * 4 + 2];
            o.w = acc[i][jh * 4 + 3];
            const float4 bb = *(const float4*)(bias + c);
            o.x += bb.x; o.y += bb.y; o.z += bb.z; o.w += bb.w;
            if (RES) {
                const float4 rv = *(const float4*)(res + r * N + c);
                o.x += rv.x; o.y += rv.y; o.z += rv.z; o.w += rv.w;
            }
            if (RELU) {
                o.x = fmaxf(o.x, 0.f); o.y = fmaxf(o.y, 0.f);
                o.z = fmaxf(o.z, 0.f); o.w = fmaxf(o.w, 0.f);
            }
            *(float4*)(C + r * N + c) = o;
        }
    }
}

// ---------------- Flash-style attention ------------------------------------
// Grid: (S/128, H, B). Block 256 threads. Q tile 128 x 64, K/V tiles 64 x 64.
// Thread map: tx = tid%8 owns k cols {j*8+tx} and out dims {tx*8..tx*8+7};
//             ty = tid/8 owns q rows {ty*4..ty*4+3}.
#define QTILE 128
#define KTILE 64
#define QS 68     // Qs row stride (floats)
#define KS 68     // Ks row stride
#define VS 64     // Vs row stride
#define PS 68     // Ps row stride
#define ATTN_SMEM ((QTILE*QS + KTILE*KS + KTILE*VS + QTILE*PS + KTILE) * 4)

__global__ void __launch_bounds__(256) attn_kernel(
    const float* __restrict__ Q, const float* __restrict__ K,
    const float* __restrict__ V, const int* __restrict__ mask,
    float* __restrict__ O)
{
    extern __shared__ float sm[];
    float* Qs = sm;                        // 128*68
    float* Ks = Qs + QTILE * QS;           // 64*68
    float* Vs = Ks + KTILE * KS;           // 64*64
    float* Ps = Vs + KTILE * VS;           // 128*68
    float* Ms = Ps + QTILE * PS;           // 64

    const int b  = blockIdx.z;
    const int h  = blockIdx.y;
    const int q0 = blockIdx.x * QTILE;
    const int tid = threadIdx.x;
    const int tx = tid & 7;
    const int ty = tid >> 3;

    // Load Q tile (128 x 64 floats = 2048 float4)
    const size_t baseQ = ((size_t)(b * S_LEN + q0)) * D_MODEL + h * DK;
    #pragma unroll
    for (int p = 0; p < 8; p++) {
        const int f = p * 256 + tid;
        const int r = f >> 4, c4 = f & 15;
        *(float4*)&Qs[r * QS + c4 * 4] =
            *(const float4*)(Q + baseQ + (size_t)r * D_MODEL + c4 * 4);
    }

    float m[4], l[4];
    #pragma unroll
    for (int i = 0; i < 4; i++) { m[i] = -1e30f; l[i] = 0.f; }
    float acc[4][8];
    #pragma unroll
    for (int i = 0; i < 4; i++)
        #pragma unroll
        for (int j = 0; j < 8; j++) acc[i][j] = 0.f;

    __syncthreads();

    for (int kt = 0; kt < S_LEN; kt += KTILE) {
        // Load K/V tiles (64 x 64 each) + mask
        const size_t baseK = ((size_t)(b * S_LEN + kt)) * D_MODEL + h * DK;
        #pragma unroll
        for (int p = 0; p < 4; p++) {
            const int f = p * 256 + tid;
            const int r = f >> 4, c4 = f & 15;
            *(float4*)&Ks[r * KS + c4 * 4] =
                *(const float4*)(K + baseK + (size_t)r * D_MODEL + c4 * 4);
            *(float4*)&Vs[r * VS + c4 * 4] =
                *(const float4*)(V + baseK + (size_t)r * D_MODEL + c4 * 4);
        }
        if (tid < KTILE)
            Ms[tid] = (mask[b * S_LEN + kt + tid] == 0) ? -1e9f : 0.f;
        __syncthreads();

        // Scores: s[i][j] for q rows ty*4+i, k cols j*8+tx
        float s[4][8];
        #pragma unroll
        for (int i = 0; i < 4; i++)
            #pragma unroll
            for (int j = 0; j < 8; j++) s[i][j] = 0.f;

        #pragma unroll
        for (int d = 0; d < DK; d += 4) {
            float4 qv[4];
            #pragma unroll
            for (int i = 0; i < 4; i++)
                qv[i] = *(const float4*)&Qs[(ty * 4 + i) * QS + d];
            #pragma unroll
            for (int j = 0; j < 8; j++) {
                const float4 kv = *(const float4*)&Ks[(j * 8 + tx) * KS + d];
                #pragma unroll
                for (int i = 0; i < 4; i++) {
                    s[i][j] = fmaf(qv[i].x, kv.x, s[i][j]);
                    s[i][j] = fmaf(qv[i].y, kv.y, s[i][j]);
                    s[i][j] = fmaf(qv[i].z, kv.z, s[i][j]);
                    s[i][j] = fmaf(qv[i].w, kv.w, s[i][j]);
                }
            }
        }
        #pragma unroll
        for (int i = 0; i < 4; i++)
            #pragma unroll
            for (int j = 0; j < 8; j++)
                s[i][j] = s[i][j] * 0.125f + Ms[j * 8 + tx];

        // Online softmax (rows reduced across the 8 tx lanes)
        #pragma unroll
        for (int i = 0; i < 4; i++) {
            float rm = s[i][0];
            #pragma unroll
            for (int j = 1; j < 8; j++) rm = fmaxf(rm, s[i][j]);
            #pragma unroll
            for (int off = 1; off < 8; off <<= 1)
                rm = fmaxf(rm, __shfl_xor_sync(0xffffffffu, rm, off));
            const float newm = fmaxf(m[i], rm);
            const float factor = __expf(m[i] - newm);
            m[i] = newm;
            float rs = 0.f;
            #pragma unroll
            for (int j = 0; j < 8; j++) {
                s[i][j] = __expf(s[i][j] - newm);
                rs += s[i][j];
            }
            #pragma unroll
            for (int off = 1; off < 8; off <<= 1)
                rs += __shfl_xor_sync(0xffffffffu, rs, off);
            l[i] = l[i] * factor + rs;
            #pragma unroll
            for (int j = 0; j < 8; j++) acc[i][j] *= factor;
            #pragma unroll
            for (int j = 0; j < 8; j++)
                Ps[(ty * 4 + i) * PS + j * 8 + tx] = s[i][j];
        }
        __syncthreads();

        // O += P @ V : thread owns (q rows ty*4+i) x (d cols tx*8..+7)
        #pragma unroll
        for (int j = 0; j < KTILE; j += 4) {
            float pa[4][4];
            #pragma unroll
            for (int i = 0; i < 4; i++)
                *(float4*)&pa[i][0] = *(const float4*)&Ps[(ty * 4 + i) * PS + j];
            #pragma unroll
            for (int jj = 0; jj < 4; jj++) {
                const float4 v0 = *(const float4*)&Vs[(j + jj) * VS + tx * 8];
                const float4 v1 = *(const float4*)&Vs[(j + jj) * VS + tx * 8 + 4];
                #pragma unroll
                for (int i = 0; i < 4; i++) {
                    const float p = pa[i][jj];
                    acc[i][0] = fmaf(p, v0.x, acc[i][0]);
                    acc[i][1] = fmaf(p, v0.y, acc[i][1]);
                    acc[i][2] = fmaf(p, v0.z, acc[i][2]);
                    acc[i][3] = fmaf(p, v0.w, acc[i][3]);
                    acc[i][4] = fmaf(p, v1.x, acc[i][4]);
                    acc[i][5] = fmaf(p, v1.y, acc[i][5]);
                    acc[i][6] = fmaf(p, v1.z, acc[i][6]);
                    acc[i][7] = fmaf(p, v1.w, acc[i][7]);
                }
            }
        }
        __syncthreads();
    }

    // Finalize: ctx[b, q, h*64 + d] = acc / l
    #pragma unroll
    for (int i = 0; i < 4; i++) {
        const float invl = 1.0f / l[i];
        const size_t q = (size_t)(b * S_LEN + q0 + ty * 4 + i);
        float* orow = O + q * D_MODEL + h * DK + tx * 8;
        float4 o0, o1;
        o0.x = acc[i][0] * invl; o0.y = acc[i][1] * invl;
        o0.z = acc[i][2] * invl; o0.w = acc[i][3] * invl;
        o1.x = acc[i][4] * invl; o1.y = acc[i][5] * invl;
        o1.z = acc[i][6] * invl; o1.w = acc[i][7] * invl;
        *(float4*)orow = o0;
        *(float4*)(orow + 4) = o1;
    }
}

// ---------------- launch ---------------------------------------------------
extern "C" void kernel_launch(void* const* d_in, const int* in_sizes, int n_in,
                              void* d_out, int out_size)
{
    const float* x   = (const float*)d_in[0];
    const int*   msk = (const int*)  d_in[1];
    const float* wq  = (const float*)d_in[2];
    const float* bq  = (const float*)d_in[3];
    const float* wk  = (const float*)d_in[4];
    const float* bk  = (const float*)d_in[5];
    const float* wv  = (const float*)d_in[6];
    const float* bv  = (const float*)d_in[7];
    const float* wo  = (const float*)d_in[8];
    const float* bo  = (const float*)d_in[9];
    const float* w1  = (const float*)d_in[10];
    const float* b1  = (const float*)d_in[11];
    const float* w2  = (const float*)d_in[12];
    const float* b2  = (const float*)d_in[13];
    const float* l1a = (const float*)d_in[14];
    const float* l1b = (const float*)d_in[15];
    const float* l2a = (const float*)d_in[16];
    const float* l2b = (const float*)d_in[17];
    float* out = (float*)d_out;

    float *xn, *q, *k, *v, *ctx, *h, *xn2, *mid;
    cudaGetSymbolAddress((void**)&xn,  g_xn);
    cudaGetSymbolAddress((void**)&q,   g_q);
    cudaGetSymbolAddress((void**)&k,   g_k);
    cudaGetSymbolAddress((void**)&v,   g_v);
    cudaGetSymbolAddress((void**)&ctx, g_ctx);
    cudaGetSymbolAddress((void**)&h,   g_h);
    cudaGetSymbolAddress((void**)&xn2, g_xn2);
    cudaGetSymbolAddress((void**)&mid, g_mid);

    cudaFuncSetAttribute(attn_kernel,
        cudaFuncAttributeMaxDynamicSharedMemorySize, ATTN_SMEM);

    // 1. ln1
    ln_kernel<<<M_ROWS, 256>>>(x, l1a, l1b, xn);
    // 2. QKV projections
    sgemm_kernel<false, false><<<dim3(D_MODEL/128, M_ROWS/128), 256>>>(
        xn, wq, bq, nullptr, q, M_ROWS, D_MODEL, D_MODEL);
    sgemm_kernel<false, false><<<dim3(D_MODEL/128, M_ROWS/128), 256>>>(
        xn, wk, bk, nullptr, k, M_ROWS, D_MODEL, D_MODEL);
    sgemm_kernel<false, false><<<dim3(D_MODEL/128, M_ROWS/128), 256>>>(
        xn, wv, bv, nullptr, v, M_ROWS, D_MODEL, D_MODEL);
    // 3. attention
    attn_kernel<<<dim3(S_LEN/QTILE, N_HEADS, B_SZ), 256, ATTN_SMEM>>>(
        q, k, v, msk, ctx);
    // 4. output projection + residual with x
    sgemm_kernel<false, true><<<dim3(D_MODEL/128, M_ROWS/128), 256>>>(
        ctx, wo, bo, x, h, M_ROWS, D_MODEL, D_MODEL);
    // 5. ln2
    ln_kernel<<<M_ROWS, 256>>>(h, l2a, l2b, xn2);
    // 6. FFN up + relu
    sgemm_kernel<true, false><<<dim3(F_FFN/128, M_ROWS/128), 256>>>(
        xn2, w1, b1, nullptr, mid, M_ROWS, F_FFN, D_MODEL);
    // 7. FFN down + residual with h -> out
    sgemm_kernel<false, true><<<dim3(D_MODEL/128, M_ROWS/128), 256>>>(
        mid, w2, b2, h, out, M_ROWS, D_MODEL, F_FFN);
}